// round 8
// baseline (speedup 1.0000x reference)
#include <cuda_runtime.h>
#include <cuda_fp16.h>
#include <cstdint>

// x[8192,256] fp32 -> loss = mean_i 1/sqrt(max(2 - 2*max_{j!=i} s_ij, 1e-30))
// s = Xn Xn^T via mma.sync m16n8k16 fp16 (f32 accum), fused row/col max.
// Persistent CTAs; cp.async pipeline rolls across tile boundaries.

#define N 8192
#define D 256
#define BM 128
#define BN 128
#define BK 64                     // K elems per stage (fp16: 128 B per row)
#define NTH 256
#define NSTAGE (D / BK)           // 4
#define STAGE_BYTES 32768         // A 16KB + B 16KB
#define SMEM_DYN (2 * STAGE_BYTES)
#define NBK (N / BN)              // 64
#define NTILES (NBK * (NBK + 1) / 2)   // 2080
#define NCTA 296                  // persistent grid (2 per SM on 148 SMs)

__device__ __half   g_xn[N * D];
__device__ unsigned g_rmax[N];

__device__ __forceinline__ unsigned encf(float f) {
    unsigned u = __float_as_uint(f);
    return (u & 0x80000000u) ? ~u : (u | 0x80000000u);
}
__device__ __forceinline__ float decf(unsigned u) {
    return (u & 0x80000000u) ? __uint_as_float(u & 0x7fffffffu) : __uint_as_float(~u);
}

__device__ __forceinline__ uint32_t smem_u32(const void* p) {
    uint32_t a;
    asm("{ .reg .u64 t; cvta.to.shared.u64 t, %1; cvt.u32.u64 %0, t; }" : "=r"(a) : "l"(p));
    return a;
}
__device__ __forceinline__ uint32_t swz(uint32_t off) { return off ^ ((off >> 3) & 0x70); }

__device__ __forceinline__ void cp16(uint32_t dst, const void* src) {
    asm volatile("cp.async.cg.shared.global [%0], [%1], 16;" :: "r"(dst), "l"(src) : "memory");
}
#define CP_COMMIT()  asm volatile("cp.async.commit_group;" ::: "memory")
#define CP_WAIT(n)   asm volatile("cp.async.wait_group %0;" :: "n"(n) : "memory")

#define LDSM_X4(R0, R1, R2, R3, ADDR) \
    asm volatile("ldmatrix.sync.aligned.m8n8.x4.shared.b16 {%0,%1,%2,%3}, [%4];" \
        : "=r"(R0), "=r"(R1), "=r"(R2), "=r"(R3) : "r"(ADDR))

#define MMA_F16(d, a, b) \
    asm volatile("mma.sync.aligned.m16n8k16.row.col.f32.f16.f16.f32 " \
        "{%0,%1,%2,%3}, {%4,%5,%6,%7}, {%8,%9}, {%0,%1,%2,%3};" \
        : "+f"((d)[0]), "+f"((d)[1]), "+f"((d)[2]), "+f"((d)[3]) \
        : "r"((a)[0]), "r"((a)[1]), "r"((a)[2]), "r"((a)[3]), \
          "r"((b)[0]), "r"((b)[1]))

__device__ __forceinline__ void unrank(int t, int& mb, int& nb) {
    int m = (int)((2.0f * NBK + 1.0f - sqrtf((2.0f * NBK + 1.0f) * (2.0f * NBK + 1.0f)
                                             - 8.0f * (float)t)) * 0.5f);
    while (m * NBK - (m * (m - 1)) / 2 > t) m--;
    while ((m + 1) * NBK - ((m + 1) * m) / 2 <= t) m++;
    mb = m;
    nb = m + (t - (m * NBK - (m * (m - 1)) / 2));
}

// ---------------------------------------------------------------------------
// Kernel 1: row L2-normalize -> fp16 (two rows per warp, MLP=4), init g_rmax.
// ---------------------------------------------------------------------------
__global__ void k_normalize(const float* __restrict__ x) {
    int gtid = blockIdx.x * blockDim.x + threadIdx.x;
    int p = gtid >> 5;                 // row pair
    int lane = threadIdx.x & 31;
    if (p < N / 2) {
        const int r0 = 2 * p, r1 = 2 * p + 1;
        const float4* xa = reinterpret_cast<const float4*>(x + (size_t)r0 * D);
        const float4* xb = reinterpret_cast<const float4*>(x + (size_t)r1 * D);
        float4 a0 = xa[lane], a1 = xa[lane + 32];
        float4 b0 = xb[lane], b1 = xb[lane + 32];
        float s0 = a0.x * a0.x + a0.y * a0.y + a0.z * a0.z + a0.w * a0.w
                 + a1.x * a1.x + a1.y * a1.y + a1.z * a1.z + a1.w * a1.w;
        float s1 = b0.x * b0.x + b0.y * b0.y + b0.z * b0.z + b0.w * b0.w
                 + b1.x * b1.x + b1.y * b1.y + b1.z * b1.z + b1.w * b1.w;
        #pragma unroll
        for (int o = 16; o; o >>= 1) {
            s0 += __shfl_xor_sync(0xFFFFFFFFu, s0, o);
            s1 += __shfl_xor_sync(0xFFFFFFFFu, s1, o);
        }
        float i0 = rsqrtf(s0), i1 = rsqrtf(s1);
        __half2* ya = reinterpret_cast<__half2*>(g_xn + (size_t)r0 * D);
        __half2* yb = reinterpret_cast<__half2*>(g_xn + (size_t)r1 * D);
        ya[lane * 2]          = __floats2half2_rn(a0.x * i0, a0.y * i0);
        ya[lane * 2 + 1]      = __floats2half2_rn(a0.z * i0, a0.w * i0);
        ya[64 + lane * 2]     = __floats2half2_rn(a1.x * i0, a1.y * i0);
        ya[64 + lane * 2 + 1] = __floats2half2_rn(a1.z * i0, a1.w * i0);
        yb[lane * 2]          = __floats2half2_rn(b0.x * i1, b0.y * i1);
        yb[lane * 2 + 1]      = __floats2half2_rn(b0.z * i1, b0.w * i1);
        yb[64 + lane * 2]     = __floats2half2_rn(b1.x * i1, b1.y * i1);
        yb[64 + lane * 2 + 1] = __floats2half2_rn(b1.z * i1, b1.w * i1);
    }
    if (gtid < N) g_rmax[gtid] = encf(-2.0f);
}

// ---------------------------------------------------------------------------
// Kernel 2: persistent tile GEMM + fused row/col max.
// ---------------------------------------------------------------------------
__global__ __launch_bounds__(NTH, 2)
void k_gemm_max() {
    extern __shared__ char dsm[];
    __shared__ unsigned redrow[BM], redcol[BN];

    const int tid  = threadIdx.x;
    const int wid  = tid >> 5;
    const int lane = tid & 31;
    const int wm   = (wid & 3) * 32;
    const int wn   = (wid >> 2) * 64;
    const uint32_t sb = smem_u32(dsm);

    // per-thread load coords (constant)
    const int lr  = tid >> 1;                 // A/B row (two 16B segs per row per pass)
    // stage loader: A 128x64, B 128x64; 8 cp16 per thread
    auto stage_load = [&](int buf, int mrow0, int nrow0, int k0) {
        uint32_t As = sb + buf * STAGE_BYTES;
        uint32_t Bs = As + 16384;
        #pragma unroll
        for (int i = 0; i < 4; i++) {
            int idx = tid + i * NTH;           // 0..1023
            int r = idx >> 3, c8 = idx & 7;
            cp16(As + swz(r * 128 + c8 * 16),
                 g_xn + (size_t)(mrow0 + r) * D + k0 + c8 * 8);
            cp16(Bs + swz(r * 128 + c8 * 16),
                 g_xn + (size_t)(nrow0 + r) * D + k0 + c8 * 8);
        }
    };
    (void)lr;

    // ldmatrix lane mapping
    const int mat  = lane >> 3;
    const int rofs = (mat & 1) * 8 + (lane & 7);
    const int ksel = mat >> 1;
    const int l7   = lane & 7;
    const int r0l  = lane >> 2;
    const int c0l  = (lane & 3) * 2;

    int t = blockIdx.x;
    if (t >= NTILES) return;
    int mb, nb;
    unrank(t, mb, nb);

    stage_load(0, mb * BM, nb * BN, 0);
    CP_COMMIT();
    int buf = 1;

    while (true) {
        const int mrow0 = mb * BM;
        const int nrow0 = nb * BN;
        const int tn = t + gridDim.x;
        const bool hasn = tn < NTILES;
        int mbn = 0, nbn = 0;
        if (hasn) unrank(tn, mbn, nbn);

        float acc[2][8][4];
        #pragma unroll
        for (int mt = 0; mt < 2; mt++)
            #pragma unroll
            for (int nt = 0; nt < 8; nt++)
                #pragma unroll
                for (int q = 0; q < 4; q++) acc[mt][nt][q] = 0.0f;

        #pragma unroll 1
        for (int s = 0; s < NSTAGE; s++) {
            if (s + 1 < NSTAGE)  { stage_load(buf, mrow0, nrow0, (s + 1) * BK); CP_COMMIT(); CP_WAIT(1); }
            else if (hasn)       { stage_load(buf, mbn * BM, nbn * BN, 0);      CP_COMMIT(); CP_WAIT(1); }
            else                 { CP_WAIT(0); }
            __syncthreads();

            const uint32_t As = sb + (buf ^ 1) * STAGE_BYTES;
            const uint32_t Bs = As + 16384;

            #pragma unroll
            for (int kk = 0; kk < 4; kk++) {
                uint32_t a[2][4];
                #pragma unroll
                for (int mt = 0; mt < 2; mt++) {
                    int row = wm + mt * 16 + rofs;
                    uint32_t ad = As + row * 128 + (((kk * 2 + ksel) ^ l7) << 4);
                    LDSM_X4(a[mt][0], a[mt][1], a[mt][2], a[mt][3], ad);
                }
                uint32_t b[8][2];
                #pragma unroll
                for (int np = 0; np < 4; np++) {
                    int row = wn + np * 16 + rofs;
                    uint32_t bd = Bs + row * 128 + (((kk * 2 + ksel) ^ l7) << 4);
                    uint32_t q0, q1, q2, q3;
                    LDSM_X4(q0, q1, q2, q3, bd);
                    b[2 * np][0] = q0;     b[2 * np][1] = q2;
                    b[2 * np + 1][0] = q1; b[2 * np + 1][1] = q3;
                }
                #pragma unroll
                for (int mt = 0; mt < 2; mt++)
                    #pragma unroll
                    for (int nt = 0; nt < 8; nt++)
                        MMA_F16(acc[mt][nt], a[mt], b[nt]);
            }
            buf ^= 1;
            __syncthreads();
        }

        // ---- fused epilogue ----
        if (tid < 128) { redrow[tid] = encf(-2.0f); redcol[tid] = encf(-2.0f); }
        __syncthreads();

        #pragma unroll
        for (int mt = 0; mt < 2; mt++)
            #pragma unroll
            for (int rh = 0; rh < 2; rh++) {
                const int lrow = wm + mt * 16 + rh * 8 + r0l;
                const int gi = mrow0 + lrow;
                float rm = -2.0f;
                #pragma unroll
                for (int nt = 0; nt < 8; nt++)
                    #pragma unroll
                    for (int bq = 0; bq < 2; bq++) {
                        int gj = nrow0 + wn + nt * 8 + c0l + bq;
                        float v = acc[mt][nt][rh * 2 + bq];
                        rm = fmaxf(rm, (gi == gj) ? -2.0f : v);
                    }
                rm = fmaxf(rm, __shfl_xor_sync(0xFFFFFFFFu, rm, 1));
                rm = fmaxf(rm, __shfl_xor_sync(0xFFFFFFFFu, rm, 2));
                if ((lane & 3) == 0) atomicMax(&redrow[lrow], encf(rm));
            }

        #pragma unroll
        for (int nt = 0; nt < 8; nt++)
            #pragma unroll
            for (int bq = 0; bq < 2; bq++) {
                const int lcol = wn + nt * 8 + c0l + bq;
                const int gj = nrow0 + lcol;
                float cm = -2.0f;
                #pragma unroll
                for (int mt = 0; mt < 2; mt++)
                    #pragma unroll
                    for (int rh = 0; rh < 2; rh++) {
                        int gi = mrow0 + wm + mt * 16 + rh * 8 + r0l;
                        float v = acc[mt][nt][rh * 2 + bq];
                        cm = fmaxf(cm, (gi == gj) ? -2.0f : v);
                    }
                cm = fmaxf(cm, __shfl_xor_sync(0xFFFFFFFFu, cm, 4));
                cm = fmaxf(cm, __shfl_xor_sync(0xFFFFFFFFu, cm, 8));
                cm = fmaxf(cm, __shfl_xor_sync(0xFFFFFFFFu, cm, 16));
                if (lane < 4) atomicMax(&redcol[lcol], encf(cm));
            }

        __syncthreads();
        if (tid < 128) {
            atomicMax(&g_rmax[mrow0 + tid], redrow[tid]);
            atomicMax(&g_rmax[nrow0 + tid], redcol[tid]);
        }
        __syncthreads();

        if (!hasn) break;
        t = tn; mb = mbn; nb = nbn;
    }
}

// ---------------------------------------------------------------------------
// Kernel 3: finalize (deterministic reduction).
// ---------------------------------------------------------------------------
__global__ void k_finalize(float* __restrict__ out) {
    __shared__ float sred[256];
    const int tid = threadIdx.x;
    float s = 0.0f;
    for (int i = tid; i < N; i += 256) {
        float smax = decf(g_rmax[i]);
        float d2 = fmaxf(2.0f - 2.0f * smax, 1e-30f);
        s += fmaxf(0.1f, rsqrtf(d2));
    }
    sred[tid] = s;
    __syncthreads();
    #pragma unroll
    for (int o = 128; o; o >>= 1) {
        if (tid < o) sred[tid] += sred[tid + o];
        __syncthreads();
    }
    if (tid == 0) out[0] = sred[0] / (float)N;
}

extern "C" void kernel_launch(void* const* d_in, const int* in_sizes, int n_in,
                              void* d_out, int out_size) {
    const float* x = (const float*)d_in[0];
    float* out = (float*)d_out;

    cudaFuncSetAttribute(k_gemm_max, cudaFuncAttributeMaxDynamicSharedMemorySize, SMEM_DYN);

    k_normalize<<<(N / 2 * 32) / 256, 256>>>(x);
    k_gemm_max<<<NCTA, NTH, SMEM_DYN>>>();
    k_finalize<<<1, 256>>>(out);
}

// round 9
// speedup vs baseline: 1.0809x; 1.0809x over previous
#include <cuda_runtime.h>
#include <cuda_fp16.h>
#include <cstdint>

// x[8192,256] fp32 -> loss = mean_i 1/sqrt(max(2 - 2*max_{j!=i} s_ij, 1e-30))
// s = Xn Xn^T via mma.sync m16n8k16 fp16 (f32 accum), fused row/col max.
// 4 warps x 64x64 warp tiles (low smem-crossbar traffic), triangular 1D grid.

#define N 8192
#define D 256
#define BM 128
#define BN 128
#define BK 64                     // K elems per stage (fp16: 128 B per row)
#define NTH 128
#define NSTAGE (D / BK)           // 4
#define STAGE_BYTES 32768         // A 16KB + B 16KB
#define SMEM_DYN (2 * STAGE_BYTES)
#define NBK (N / BN)              // 64
#define NTILES (NBK * (NBK + 1) / 2)   // 2080

__device__ __half   g_xn[N * D];
__device__ unsigned g_rmax[N];

__device__ __forceinline__ unsigned encf(float f) {
    unsigned u = __float_as_uint(f);
    return (u & 0x80000000u) ? ~u : (u | 0x80000000u);
}
__device__ __forceinline__ float decf(unsigned u) {
    return (u & 0x80000000u) ? __uint_as_float(u & 0x7fffffffu) : __uint_as_float(~u);
}

__device__ __forceinline__ uint32_t smem_u32(const void* p) {
    uint32_t a;
    asm("{ .reg .u64 t; cvta.to.shared.u64 t, %1; cvt.u32.u64 %0, t; }" : "=r"(a) : "l"(p));
    return a;
}
__device__ __forceinline__ uint32_t swz(uint32_t off) { return off ^ ((off >> 3) & 0x70); }

__device__ __forceinline__ void cp16(uint32_t dst, const void* src) {
    asm volatile("cp.async.cg.shared.global [%0], [%1], 16;" :: "r"(dst), "l"(src) : "memory");
}
#define CP_COMMIT()  asm volatile("cp.async.commit_group;" ::: "memory")
#define CP_WAIT(n)   asm volatile("cp.async.wait_group %0;" :: "n"(n) : "memory")

#define LDSM_X4(R0, R1, R2, R3, ADDR) \
    asm volatile("ldmatrix.sync.aligned.m8n8.x4.shared.b16 {%0,%1,%2,%3}, [%4];" \
        : "=r"(R0), "=r"(R1), "=r"(R2), "=r"(R3) : "r"(ADDR))

#define MMA_F16(d, a, b) \
    asm volatile("mma.sync.aligned.m16n8k16.row.col.f32.f16.f16.f32 " \
        "{%0,%1,%2,%3}, {%4,%5,%6,%7}, {%8,%9}, {%0,%1,%2,%3};" \
        : "+f"((d)[0]), "+f"((d)[1]), "+f"((d)[2]), "+f"((d)[3]) \
        : "r"((a)[0]), "r"((a)[1]), "r"((a)[2]), "r"((a)[3]), \
          "r"((b)[0]), "r"((b)[1]))

// ---------------------------------------------------------------------------
// Kernel 1: row L2-normalize -> fp16, init g_rmax.
// ---------------------------------------------------------------------------
__global__ void k_normalize(const float* __restrict__ x) {
    int gtid = blockIdx.x * blockDim.x + threadIdx.x;
    int row = gtid >> 5;
    int lane = threadIdx.x & 31;
    if (row < N) {
        const float4* xr = reinterpret_cast<const float4*>(x + (size_t)row * D);
        float4 v0 = xr[lane], v1 = xr[lane + 32];
        float ss = v0.x * v0.x + v0.y * v0.y + v0.z * v0.z + v0.w * v0.w +
                   v1.x * v1.x + v1.y * v1.y + v1.z * v1.z + v1.w * v1.w;
        #pragma unroll
        for (int o = 16; o; o >>= 1) ss += __shfl_xor_sync(0xFFFFFFFFu, ss, o);
        float inv = rsqrtf(ss);
        __half2* xo = reinterpret_cast<__half2*>(g_xn + (size_t)row * D);
        xo[lane * 2]          = __floats2half2_rn(v0.x * inv, v0.y * inv);
        xo[lane * 2 + 1]      = __floats2half2_rn(v0.z * inv, v0.w * inv);
        xo[64 + lane * 2]     = __floats2half2_rn(v1.x * inv, v1.y * inv);
        xo[64 + lane * 2 + 1] = __floats2half2_rn(v1.z * inv, v1.w * inv);
    }
    if (gtid < N) g_rmax[gtid] = encf(-2.0f);
}

// ---------------------------------------------------------------------------
// Kernel 2: 128x128 tile of S, 4 warps of 64x64, fused row/col max.
// ---------------------------------------------------------------------------
__global__ __launch_bounds__(NTH, 2)
void k_gemm_max() {
    // unrank triangular index
    const int t = blockIdx.x;
    int mb = (int)((2.0f * NBK + 1.0f - sqrtf((2.0f * NBK + 1.0f) * (2.0f * NBK + 1.0f)
                                              - 8.0f * (float)t)) * 0.5f);
    while (mb * NBK - (mb * (mb - 1)) / 2 > t) mb--;
    while ((mb + 1) * NBK - ((mb + 1) * mb) / 2 <= t) mb++;
    const int nb = mb + (t - (mb * NBK - (mb * (mb - 1)) / 2));

    extern __shared__ char dsm[];
    __shared__ unsigned redrow[BM], redcol[BN];

    const int tid  = threadIdx.x;
    const int wid  = tid >> 5;
    const int lane = tid & 31;
    const int wm   = (wid & 1) * 64;   // warp M offset
    const int wn   = (wid >> 1) * 64;  // warp N offset
    const int mrow0 = mb * BM;
    const int nrow0 = nb * BN;

    redrow[tid] = encf(-2.0f);
    redcol[tid] = encf(-2.0f);

    const uint32_t sb = smem_u32(dsm);

    // stage loader: A 128x64 (16KB = 1024 16B segs), B same; 16 cp16/thread
    auto stage_load = [&](int buf, int k0) {
        uint32_t As = sb + buf * STAGE_BYTES;
        uint32_t Bs = As + 16384;
        #pragma unroll
        for (int i = 0; i < 8; i++) {
            int idx = tid + i * NTH;            // 0..1023
            int r = idx >> 3, c8 = idx & 7;
            cp16(As + swz(r * 128 + c8 * 16),
                 g_xn + (size_t)(mrow0 + r) * D + k0 + c8 * 8);
            cp16(Bs + swz(r * 128 + c8 * 16),
                 g_xn + (size_t)(nrow0 + r) * D + k0 + c8 * 8);
        }
    };

    float acc[4][8][4];
    #pragma unroll
    for (int mt = 0; mt < 4; mt++)
        #pragma unroll
        for (int nt = 0; nt < 8; nt++)
            #pragma unroll
            for (int q = 0; q < 4; q++) acc[mt][nt][q] = 0.0f;

    // ldmatrix lane mapping: matrix = lane>>3; row within m16 = (mat&1)*8 + (lane&7)
    const int mat  = lane >> 3;
    const int rofs = (mat & 1) * 8 + (lane & 7);
    const int ksel = mat >> 1;            // k-segment select
    const int l7   = lane & 7;

    stage_load(0, 0);
    CP_COMMIT();

    #pragma unroll 1
    for (int s = 0; s < NSTAGE; s++) {
        if (s + 1 < NSTAGE) { stage_load((s + 1) & 1, (s + 1) * BK); CP_COMMIT(); CP_WAIT(1); }
        else                { CP_WAIT(0); }
        __syncthreads();

        const uint32_t As = sb + (s & 1) * STAGE_BYTES;
        const uint32_t Bs = As + 16384;

        #pragma unroll
        for (int kk = 0; kk < 4; kk++) {       // 4 x k16 steps
            uint32_t a[4][4];
            #pragma unroll
            for (int mt = 0; mt < 4; mt++) {
                int row = wm + mt * 16 + rofs;
                uint32_t ad = As + row * 128 + (((kk * 2 + ksel) ^ l7) << 4);
                LDSM_X4(a[mt][0], a[mt][1], a[mt][2], a[mt][3], ad);
            }
            uint32_t b[8][2];
            #pragma unroll
            for (int np = 0; np < 4; np++) {   // n16 blocks
                int row = wn + np * 16 + rofs;
                uint32_t bd = Bs + row * 128 + (((kk * 2 + ksel) ^ l7) << 4);
                uint32_t q0, q1, q2, q3;
                LDSM_X4(q0, q1, q2, q3, bd);
                b[2 * np][0] = q0;     b[2 * np][1] = q2;
                b[2 * np + 1][0] = q1; b[2 * np + 1][1] = q3;
            }
            #pragma unroll
            for (int mt = 0; mt < 4; mt++)
                #pragma unroll
                for (int nt = 0; nt < 8; nt++)
                    MMA_F16(acc[mt][nt], a[mt], b[nt]);
        }
        __syncthreads();
    }

    // ---- fused epilogue (acc frag: r = lane>>2 + rh*8, c = (lane&3)*2 + bq) ----
    const int r0 = lane >> 2;
    const int c0 = (lane & 3) * 2;

    #pragma unroll
    for (int mt = 0; mt < 4; mt++)
        #pragma unroll
        for (int rh = 0; rh < 2; rh++) {
            const int lrow = wm + mt * 16 + rh * 8 + r0;
            const int gi = mrow0 + lrow;
            float rm = -2.0f;
            #pragma unroll
            for (int nt = 0; nt < 8; nt++)
                #pragma unroll
                for (int bq = 0; bq < 2; bq++) {
                    int gj = nrow0 + wn + nt * 8 + c0 + bq;
                    float v = acc[mt][nt][rh * 2 + bq];
                    rm = fmaxf(rm, (gi == gj) ? -2.0f : v);
                }
            rm = fmaxf(rm, __shfl_xor_sync(0xFFFFFFFFu, rm, 1));
            rm = fmaxf(rm, __shfl_xor_sync(0xFFFFFFFFu, rm, 2));
            if ((lane & 3) == 0) atomicMax(&redrow[lrow], encf(rm));
        }

    #pragma unroll
    for (int nt = 0; nt < 8; nt++)
        #pragma unroll
        for (int bq = 0; bq < 2; bq++) {
            const int lcol = wn + nt * 8 + c0 + bq;
            const int gj = nrow0 + lcol;
            float cm = -2.0f;
            #pragma unroll
            for (int mt = 0; mt < 4; mt++)
                #pragma unroll
                for (int rh = 0; rh < 2; rh++) {
                    int gi = mrow0 + wm + mt * 16 + rh * 8 + r0;
                    float v = acc[mt][nt][rh * 2 + bq];
                    cm = fmaxf(cm, (gi == gj) ? -2.0f : v);
                }
            cm = fmaxf(cm, __shfl_xor_sync(0xFFFFFFFFu, cm, 4));
            cm = fmaxf(cm, __shfl_xor_sync(0xFFFFFFFFu, cm, 8));
            cm = fmaxf(cm, __shfl_xor_sync(0xFFFFFFFFu, cm, 16));
            if (lane < 4) atomicMax(&redcol[lcol], encf(cm));
        }

    __syncthreads();
    atomicMax(&g_rmax[mrow0 + tid], redrow[tid]);
    atomicMax(&g_rmax[nrow0 + tid], redcol[tid]);
}

// ---------------------------------------------------------------------------
// Kernel 3: finalize (deterministic reduction).
// ---------------------------------------------------------------------------
__global__ void k_finalize(float* __restrict__ out) {
    __shared__ float sred[256];
    const int tid = threadIdx.x;
    float s = 0.0f;
    for (int i = tid; i < N; i += 256) {
        float smax = decf(g_rmax[i]);
        float d2 = fmaxf(2.0f - 2.0f * smax, 1e-30f);
        s += fmaxf(0.1f, rsqrtf(d2));
    }
    sred[tid] = s;
    __syncthreads();
    #pragma unroll
    for (int o = 128; o; o >>= 1) {
        if (tid < o) sred[tid] += sred[tid + o];
        __syncthreads();
    }
    if (tid == 0) out[0] = sred[0] / (float)N;
}

extern "C" void kernel_launch(void* const* d_in, const int* in_sizes, int n_in,
                              void* d_out, int out_size) {
    const float* x = (const float*)d_in[0];
    float* out = (float*)d_out;

    cudaFuncSetAttribute(k_gemm_max, cudaFuncAttributeMaxDynamicSharedMemorySize, SMEM_DYN);

    k_normalize<<<(N * 32) / 256, 256>>>(x);
    k_gemm_max<<<NTILES, NTH, SMEM_DYN>>>();
    k_finalize<<<1, 256>>>(out);
}

// round 12
// speedup vs baseline: 1.0890x; 1.0075x over previous
#include <cuda_runtime.h>
#include <cuda_fp16.h>
#include <cstdint>

// x[8192,256] fp32 -> loss = mean_i 1/sqrt(max(2 - 2*max_{j!=i} s_ij, 1e-30))
// s = Xn Xn^T via mma.sync m16n8k16 fp16 (f32 accum), fused row/col max.
// GEMM config = round-7 best (8 warps, 32x64 warp tiles, triangular 1D grid).
// This round: high-MLP normalize + hierarchical finalize.

#define N 8192
#define D 256
#define BM 128
#define BN 128
#define BK 64                     // K elems per stage (fp16: 128 B per row)
#define NTH 256
#define NSTAGE (D / BK)           // 4
#define STAGE_BYTES 32768         // A 16KB + B 16KB
#define SMEM_DYN (2 * STAGE_BYTES)
#define NBK (N / BN)              // 64
#define NTILES (NBK * (NBK + 1) / 2)   // 2080

__device__ __half   g_xn[N * D];
__device__ unsigned g_rmax[N];
__device__ float    g_part[32];

__device__ __forceinline__ unsigned encf(float f) {
    unsigned u = __float_as_uint(f);
    return (u & 0x80000000u) ? ~u : (u | 0x80000000u);
}
__device__ __forceinline__ float decf(unsigned u) {
    return (u & 0x80000000u) ? __uint_as_float(u & 0x7fffffffu) : __uint_as_float(~u);
}

__device__ __forceinline__ uint32_t smem_u32(const void* p) {
    uint32_t a;
    asm("{ .reg .u64 t; cvta.to.shared.u64 t, %1; cvt.u32.u64 %0, t; }" : "=r"(a) : "l"(p));
    return a;
}
__device__ __forceinline__ uint32_t swz(uint32_t off) { return off ^ ((off >> 3) & 0x70); }

__device__ __forceinline__ void cp16(uint32_t dst, const void* src) {
    asm volatile("cp.async.cg.shared.global [%0], [%1], 16;" :: "r"(dst), "l"(src) : "memory");
}
#define CP_COMMIT()  asm volatile("cp.async.commit_group;" ::: "memory")
#define CP_WAIT(n)   asm volatile("cp.async.wait_group %0;" :: "n"(n) : "memory")

#define LDSM_X4(R0, R1, R2, R3, ADDR) \
    asm volatile("ldmatrix.sync.aligned.m8n8.x4.shared.b16 {%0,%1,%2,%3}, [%4];" \
        : "=r"(R0), "=r"(R1), "=r"(R2), "=r"(R3) : "r"(ADDR))

#define MMA_F16(d, a, b) \
    asm volatile("mma.sync.aligned.m16n8k16.row.col.f32.f16.f16.f32 " \
        "{%0,%1,%2,%3}, {%4,%5,%6,%7}, {%8,%9}, {%0,%1,%2,%3};" \
        : "+f"((d)[0]), "+f"((d)[1]), "+f"((d)[2]), "+f"((d)[3]) \
        : "r"((a)[0]), "r"((a)[1]), "r"((a)[2]), "r"((a)[3]), \
          "r"((b)[0]), "r"((b)[1]))

struct alignas(16) H8 { __half2 h[4]; };

// ---------------------------------------------------------------------------
// Kernel 1: L2-normalize -> fp16. Two rows per warp (MLP=4), STG.128 stores.
// Lane l covers elems [8l, 8l+8) of each row.
// ---------------------------------------------------------------------------
__global__ void k_normalize(const float* __restrict__ x) {
    int gtid = blockIdx.x * blockDim.x + threadIdx.x;
    int p = gtid >> 5;
    int lane = threadIdx.x & 31;
    if (p < N / 2) {
        const int r0 = 2 * p, r1 = 2 * p + 1;
        const float4* xa = reinterpret_cast<const float4*>(x + (size_t)r0 * D);
        const float4* xb = reinterpret_cast<const float4*>(x + (size_t)r1 * D);
        float4 a0 = xa[2 * lane], a1 = xa[2 * lane + 1];
        float4 b0 = xb[2 * lane], b1 = xb[2 * lane + 1];
        float s0 = a0.x * a0.x + a0.y * a0.y + a0.z * a0.z + a0.w * a0.w
                 + a1.x * a1.x + a1.y * a1.y + a1.z * a1.z + a1.w * a1.w;
        float s1 = b0.x * b0.x + b0.y * b0.y + b0.z * b0.z + b0.w * b0.w
                 + b1.x * b1.x + b1.y * b1.y + b1.z * b1.z + b1.w * b1.w;
        #pragma unroll
        for (int o = 16; o; o >>= 1) {
            s0 += __shfl_xor_sync(0xFFFFFFFFu, s0, o);
            s1 += __shfl_xor_sync(0xFFFFFFFFu, s1, o);
        }
        float i0 = rsqrtf(s0), i1 = rsqrtf(s1);
        H8 va, vb;
        va.h[0] = __floats2half2_rn(a0.x * i0, a0.y * i0);
        va.h[1] = __floats2half2_rn(a0.z * i0, a0.w * i0);
        va.h[2] = __floats2half2_rn(a1.x * i0, a1.y * i0);
        va.h[3] = __floats2half2_rn(a1.z * i0, a1.w * i0);
        vb.h[0] = __floats2half2_rn(b0.x * i1, b0.y * i1);
        vb.h[1] = __floats2half2_rn(b0.z * i1, b0.w * i1);
        vb.h[2] = __floats2half2_rn(b1.x * i1, b1.y * i1);
        vb.h[3] = __floats2half2_rn(b1.z * i1, b1.w * i1);
        reinterpret_cast<H8*>(g_xn + (size_t)r0 * D)[lane] = va;
        reinterpret_cast<H8*>(g_xn + (size_t)r1 * D)[lane] = vb;
    }
    if (gtid < N) g_rmax[gtid] = encf(-2.0f);
}

// ---------------------------------------------------------------------------
// Kernel 2: 128x128 tile of S via mma.sync fp16, fused row/col max.
// (round-7 configuration, unchanged)
// ---------------------------------------------------------------------------
__global__ __launch_bounds__(NTH, 2)
void k_gemm_max() {
    const int t = blockIdx.x;
    int mb = (int)((2.0f * NBK + 1.0f - sqrtf((2.0f * NBK + 1.0f) * (2.0f * NBK + 1.0f)
                                              - 8.0f * (float)t)) * 0.5f);
    while (mb * NBK - (mb * (mb - 1)) / 2 > t) mb--;
    while ((mb + 1) * NBK - ((mb + 1) * mb) / 2 <= t) mb++;
    const int nb = mb + (t - (mb * NBK - (mb * (mb - 1)) / 2));

    extern __shared__ char dsm[];
    __shared__ unsigned redrow[BM], redcol[BN];

    const int tid  = threadIdx.x;
    const int wid  = tid >> 5;
    const int lane = tid & 31;
    const int wm   = (wid & 3) * 32;   // warp M offset
    const int wn   = (wid >> 2) * 64;  // warp N offset
    const int mrow0 = mb * BM;
    const int nrow0 = nb * BN;

    if (tid < 128) { redrow[tid] = encf(-2.0f); redcol[tid] = encf(-2.0f); }

    const uint32_t sb = smem_u32(dsm);

    auto stage_load = [&](int buf, int k0) {
        uint32_t As = sb + buf * STAGE_BYTES;
        uint32_t Bs = As + 16384;
        #pragma unroll
        for (int i = 0; i < 4; i++) {
            int idx = tid + i * NTH;            // 0..1023
            int r = idx >> 3, c8 = idx & 7;
            cp16(As + swz(r * 128 + c8 * 16),
                 g_xn + (size_t)(mrow0 + r) * D + k0 + c8 * 8);
            cp16(Bs + swz(r * 128 + c8 * 16),
                 g_xn + (size_t)(nrow0 + r) * D + k0 + c8 * 8);
        }
    };

    float acc[2][8][4];
    #pragma unroll
    for (int mt = 0; mt < 2; mt++)
        #pragma unroll
        for (int nt = 0; nt < 8; nt++)
            #pragma unroll
            for (int q = 0; q < 4; q++) acc[mt][nt][q] = 0.0f;

    const int mat  = lane >> 3;
    const int rofs = (mat & 1) * 8 + (lane & 7);
    const int ksel = mat >> 1;
    const int l7   = lane & 7;

    stage_load(0, 0);
    CP_COMMIT();

    #pragma unroll 1
    for (int s = 0; s < NSTAGE; s++) {
        if (s + 1 < NSTAGE) { stage_load((s + 1) & 1, (s + 1) * BK); CP_COMMIT(); CP_WAIT(1); }
        else                { CP_WAIT(0); }
        __syncthreads();

        const uint32_t As = sb + (s & 1) * STAGE_BYTES;
        const uint32_t Bs = As + 16384;

        #pragma unroll
        for (int kk = 0; kk < 4; kk++) {
            uint32_t a[2][4];
            #pragma unroll
            for (int mt = 0; mt < 2; mt++) {
                int row = wm + mt * 16 + rofs;
                uint32_t ad = As + row * 128 + (((kk * 2 + ksel) ^ l7) << 4);
                LDSM_X4(a[mt][0], a[mt][1], a[mt][2], a[mt][3], ad);
            }
            uint32_t b[8][2];
            #pragma unroll
            for (int np = 0; np < 4; np++) {
                int row = wn + np * 16 + rofs;
                uint32_t bd = Bs + row * 128 + (((kk * 2 + ksel) ^ l7) << 4);
                uint32_t q0, q1, q2, q3;
                LDSM_X4(q0, q1, q2, q3, bd);
                b[2 * np][0] = q0;     b[2 * np][1] = q2;
                b[2 * np + 1][0] = q1; b[2 * np + 1][1] = q3;
            }
            #pragma unroll
            for (int mt = 0; mt < 2; mt++)
                #pragma unroll
                for (int nt = 0; nt < 8; nt++)
                    MMA_F16(acc[mt][nt], a[mt], b[nt]);
        }
        __syncthreads();
    }

    // ---- fused epilogue ----
    const int r0 = lane >> 2;
    const int c0 = (lane & 3) * 2;

    #pragma unroll
    for (int mt = 0; mt < 2; mt++)
        #pragma unroll
        for (int rh = 0; rh < 2; rh++) {
            const int lrow = wm + mt * 16 + rh * 8 + r0;
            const int gi = mrow0 + lrow;
            float rm = -2.0f;
            #pragma unroll
            for (int nt = 0; nt < 8; nt++)
                #pragma unroll
                for (int bq = 0; bq < 2; bq++) {
                    int gj = nrow0 + wn + nt * 8 + c0 + bq;
                    float v = acc[mt][nt][rh * 2 + bq];
                    rm = fmaxf(rm, (gi == gj) ? -2.0f : v);
                }
            rm = fmaxf(rm, __shfl_xor_sync(0xFFFFFFFFu, rm, 1));
            rm = fmaxf(rm, __shfl_xor_sync(0xFFFFFFFFu, rm, 2));
            if ((lane & 3) == 0) atomicMax(&redrow[lrow], encf(rm));
        }

    #pragma unroll
    for (int nt = 0; nt < 8; nt++)
        #pragma unroll
        for (int bq = 0; bq < 2; bq++) {
            const int lcol = wn + nt * 8 + c0 + bq;
            const int gj = nrow0 + lcol;
            float cm = -2.0f;
            #pragma unroll
            for (int mt = 0; mt < 2; mt++)
                #pragma unroll
                for (int rh = 0; rh < 2; rh++) {
                    int gi = mrow0 + wm + mt * 16 + rh * 8 + r0;
                    float v = acc[mt][nt][rh * 2 + bq];
                    cm = fmaxf(cm, (gi == gj) ? -2.0f : v);
                }
            cm = fmaxf(cm, __shfl_xor_sync(0xFFFFFFFFu, cm, 4));
            cm = fmaxf(cm, __shfl_xor_sync(0xFFFFFFFFu, cm, 8));
            cm = fmaxf(cm, __shfl_xor_sync(0xFFFFFFFFu, cm, 16));
            if (lane < 4) atomicMax(&redcol[lcol], encf(cm));
        }

    __syncthreads();
    if (tid < 128) {
        atomicMax(&g_rmax[mrow0 + tid], redrow[tid]);
        atomicMax(&g_rmax[nrow0 + tid], redcol[tid]);
    }
}

// ---------------------------------------------------------------------------
// Kernel 3a: per-block partial loss sums (32 blocks x 256 rows).
// ---------------------------------------------------------------------------
__global__ void k_rowloss() {
    __shared__ float sred[256];
    const int tid = threadIdx.x;
    const int i = blockIdx.x * 256 + tid;
    float smax = decf(g_rmax[i]);
    float d2 = fmaxf(2.0f - 2.0f * smax, 1e-30f);
    sred[tid] = fmaxf(0.1f, rsqrtf(d2));
    __syncthreads();
    #pragma unroll
    for (int o = 128; o; o >>= 1) {
        if (tid < o) sred[tid] += sred[tid + o];
        __syncthreads();
    }
    if (tid == 0) g_part[blockIdx.x] = sred[0];
}

// ---------------------------------------------------------------------------
// Kernel 3b: final mean over 32 partials.
// ---------------------------------------------------------------------------
__global__ void k_finalize(float* __restrict__ out) {
    const int lane = threadIdx.x;
    float s = g_part[lane];
    #pragma unroll
    for (int o = 16; o; o >>= 1) s += __shfl_xor_sync(0xFFFFFFFFu, s, o);
    if (lane == 0) out[0] = s / (float)N;
}

extern "C" void kernel_launch(void* const* d_in, const int* in_sizes, int n_in,
                              void* d_out, int out_size) {
    const float* x = (const float*)d_in[0];
    float* out = (float*)d_out;

    cudaFuncSetAttribute(k_gemm_max, cudaFuncAttributeMaxDynamicSharedMemorySize, SMEM_DYN);

    k_normalize<<<(N / 2 * 32) / 256, 256>>>(x);
    k_gemm_max<<<NTILES, NTH, SMEM_DYN>>>();
    k_rowloss<<<32, 256>>>();
    k_finalize<<<1, 32>>>(out);
}